// round 9
// baseline (speedup 1.0000x reference)
#include <cuda_runtime.h>

#define NV   8192
#define FEAT 256
#define HIDD 64
#define ALPHA_S 0.2f
#define JSPLIT 4
#define JCHUNK (NV / JSPLIT)   // 2048

// Scratch (device globals: no allocation allowed)
__device__ float g_h[NV * HIDD];                 // 2 MB
__device__ float g_ssrc[NV];
__device__ float g_sdst[NV];
__device__ float g_acc[JSPLIT][NV * HIDD];       // 8 MB partial accumulators
__device__ float g_l[JSPLIT][NV];                // partial softmax denominators

// ---------------- packed f32x2 helpers (Blackwell FFMA2) ----------------
__device__ __forceinline__ unsigned long long pack2(float w) {
    unsigned long long r;
    asm("mov.b64 %0, {%1, %1};" : "=l"(r) : "f"(w));
    return r;
}
__device__ __forceinline__ void fma2(unsigned long long& d,
                                     unsigned long long a,
                                     unsigned long long b) {
    asm("fma.rn.f32x2 %0, %1, %2, %0;" : "+l"(d) : "l"(a), "l"(b));
}
__device__ __forceinline__ float2 unpack2(unsigned long long v) {
    float2 r;
    asm("mov.b64 {%0, %1}, %2;" : "=f"(r.x), "=f"(r.y) : "l"(v));
    return r;
}

// ---------------- Kernel 1: h = X @ W  (8192x256 @ 256x64) ----------------
__global__ __launch_bounds__(256) void k_gemm_h(const float* __restrict__ X,
                                                const float* __restrict__ W) {
    __shared__ __align__(16) float Xs[64 * 68];   // padded: stride 68 avoids bank conflicts
    __shared__ __align__(16) float Ws[64 * 64];
    const int t  = threadIdx.x;
    const int rb = blockIdx.x * 64;
    const int r  = t >> 2;          // 0..63 row within tile
    const int q  = t & 3;           // col group: 16 cols each

    float acc[16];
#pragma unroll
    for (int i = 0; i < 16; i++) acc[i] = 0.f;

    for (int kc = 0; kc < FEAT; kc += 64) {
#pragma unroll
        for (int k = 0; k < 4; k++) {
            int p = t + 256 * k;
            int row = p >> 4, c4 = p & 15;
            float4 v = *(const float4*)&X[(size_t)(rb + row) * FEAT + kc + c4 * 4];
            *(float4*)&Xs[row * 68 + c4 * 4] = v;
        }
#pragma unroll
        for (int k = 0; k < 4; k++) {
            int p = t + 256 * k;
            int row = p >> 4, c4 = p & 15;
            float4 v = *(const float4*)&W[(size_t)(kc + row) * HIDD + c4 * 4];
            *(float4*)&Ws[row * 64 + c4 * 4] = v;
        }
        __syncthreads();
#pragma unroll 16
        for (int k = 0; k < 64; k++) {
            float x = Xs[r * 68 + k];
#pragma unroll
            for (int g = 0; g < 4; g++) {
                float4 wv = *(const float4*)&Ws[k * 64 + q * 16 + g * 4];
                acc[g * 4 + 0] = fmaf(x, wv.x, acc[g * 4 + 0]);
                acc[g * 4 + 1] = fmaf(x, wv.y, acc[g * 4 + 1]);
                acc[g * 4 + 2] = fmaf(x, wv.z, acc[g * 4 + 2]);
                acc[g * 4 + 3] = fmaf(x, wv.w, acc[g * 4 + 3]);
            }
        }
        __syncthreads();
    }
#pragma unroll
    for (int g = 0; g < 4; g++) {
        *(float4*)&g_h[(size_t)(rb + r) * HIDD + q * 16 + g * 4] =
            make_float4(acc[g * 4], acc[g * 4 + 1], acc[g * 4 + 2], acc[g * 4 + 3]);
    }
}

// ---------------- Kernel 2: s_src/s_dst = h . a[:H] / h . a[H:] ----------------
__global__ __launch_bounds__(256) void k_s(const float* __restrict__ a) {
    const int warp = threadIdx.x >> 5, lane = threadIdx.x & 31;
    const int row = blockIdx.x * 8 + warp;
    float h0 = g_h[(size_t)row * HIDD + lane];
    float h1 = g_h[(size_t)row * HIDD + 32 + lane];
    float ps = h0 * a[lane] + h1 * a[32 + lane];
    float pd = h0 * a[64 + lane] + h1 * a[96 + lane];
#pragma unroll
    for (int o = 16; o; o >>= 1) {
        ps += __shfl_xor_sync(0xffffffffu, ps, o);
        pd += __shfl_xor_sync(0xffffffffu, pd, o);
    }
    if (lane == 0) { g_ssrc[row] = ps; g_sdst[row] = pd; }
}

// ---------------- Kernel 3: fused mask + exp + weighted aggregation ----------------
// Softmax without max-shift (|e| bounded, exp stays finite in fp32):
//   l_i   = sum_j adj_ij * exp(leaky(s_i + s_j))
//   acc_i = sum_j adj_ij * exp(leaky(s_i + s_j)) * h_j
// One pass over adj (read exactly once, 256 MB).
__global__ __launch_bounds__(256, 4) void k_main(const int* __restrict__ adj) {
    __shared__ __align__(16) float hs[64 * 64];   // h tile, [j][d]
    __shared__ float ws[64 * 65];                 // w tile, padded stride 65
    __shared__ float ssrc_s[64];

    const int t  = threadIdx.x;
    const int ti = t >> 4;        // 0..15 -> rows ti*4..ti*4+3
    const int td = t & 15;        // 0..15 -> dims/cols td*4..td*4+3
    const int rb = blockIdx.x * 64;
    const int split = blockIdx.y;
    const int j0 = split * JCHUNK;

    if (t < 64) ssrc_s[t] = g_ssrc[rb + t];
    __syncthreads();

    unsigned long long acc[4][2];
#pragma unroll
    for (int a0 = 0; a0 < 4; a0++) { acc[a0][0] = 0ull; acc[a0][1] = 0ull; }
    float lp[4] = {0.f, 0.f, 0.f, 0.f};

    for (int jb = j0; jb < j0 + JCHUNK; jb += 64) {
        // stage h tile (L2-resident, 16 KB)
#pragma unroll
        for (int k = 0; k < 4; k++) {
            int p = t + 256 * k;
            int row = p >> 4, c4 = p & 15;
            *(float4*)&hs[row * 64 + c4 * 4] =
                *(const float4*)&g_h[(size_t)(jb + row) * HIDD + c4 * 4];
        }
        // compute 4x4 weight block
        float4 sd = *(const float4*)&g_sdst[jb + td * 4];
        float sdv[4] = {sd.x, sd.y, sd.z, sd.w};
#pragma unroll
        for (int a0 = 0; a0 < 4; a0++) {
            const int i = ti * 4 + a0;
            int4 av = *(const int4*)&adj[(size_t)(rb + i) * NV + jb + td * 4];
            int am[4] = {av.x, av.y, av.z, av.w};
            float ss = ssrc_s[i];
#pragma unroll
            for (int b = 0; b < 4; b++) {
                float e = ss + sdv[b];
                e = e > 0.f ? e : ALPHA_S * e;
                float w = (am[b] > 0) ? __expf(e) : 0.f;
                ws[i * 65 + td * 4 + b] = w;
                lp[a0] += w;
            }
        }
        __syncthreads();
        // aggregation: acc[4 rows][4 dims] += w * h, packed f32x2
#pragma unroll 16
        for (int jj = 0; jj < 64; jj++) {
            ulonglong2 hv = *(const ulonglong2*)&hs[jj * 64 + td * 4];
#pragma unroll
            for (int a0 = 0; a0 < 4; a0++) {
                unsigned long long w2 = pack2(ws[(ti * 4 + a0) * 65 + jj]);
                fma2(acc[a0][0], w2, hv.x);
                fma2(acc[a0][1], w2, hv.y);
            }
        }
        __syncthreads();
    }

    // write partial accumulators
#pragma unroll
    for (int a0 = 0; a0 < 4; a0++) {
        float2 lo = unpack2(acc[a0][0]);
        float2 hi = unpack2(acc[a0][1]);
        *(float4*)&g_acc[split][(size_t)(rb + ti * 4 + a0) * HIDD + td * 4] =
            make_float4(lo.x, lo.y, hi.x, hi.y);
    }
    // reduce per-row l across the 16 td-threads (reuse ws)
#pragma unroll
    for (int a0 = 0; a0 < 4; a0++) ws[(ti * 4 + a0) * 65 + td] = lp[a0];
    __syncthreads();
    if (t < 64) {
        float s = 0.f;
#pragma unroll
        for (int k = 0; k < 16; k++) s += ws[t * 65 + k];
        g_l[split][rb + t] = s;
    }
}

// ---------------- Kernel 4: out = relu( (sum_s acc) / (sum_s l) ) ----------------
__global__ __launch_bounds__(256) void k_final(float* __restrict__ out) {
    int idx = blockIdx.x * 256 + threadIdx.x;
    if (idx >= NV * HIDD) return;
    int row = idx >> 6;
    float l = g_l[0][row] + g_l[1][row] + g_l[2][row] + g_l[3][row];
    float v = (g_acc[0][idx] + g_acc[1][idx] + g_acc[2][idx] + g_acc[3][idx]) / l;
    out[idx] = v > 0.f ? v : 0.f;
}

extern "C" void kernel_launch(void* const* d_in, const int* in_sizes, int n_in,
                              void* d_out, int out_size) {
    const float* X   = (const float*)d_in[0];      // inputs [N, FEAT]
    const int*   adj = (const int*)  d_in[1];      // adj [N, N]
    // d_in[2] tree_attention: unused by reference
    const float* W   = (const float*)d_in[3];      // W [FEAT, HID]
    const float* a   = (const float*)d_in[4];      // a [2*HID, 1]
    float* out = (float*)d_out;

    k_gemm_h<<<NV / 64, 256>>>(X, W);
    k_s<<<NV / 8, 256>>>(a);
    k_main<<<dim3(NV / 64, JSPLIT), 256>>>(adj);
    k_final<<<(NV * HIDD + 255) / 256, 256>>>(out);
}